// round 9
// baseline (speedup 1.0000x reference)
#include <cuda_runtime.h>

// ---------------------------------------------------------------------------
// 2-D elastic staggered-grid FDTD, persistent kernel, k=2 time blocking,
// tagged-chunk single-RTT neighbor exchange (R8) + PACKED f32x2 compute:
// rows (0,1),(2,3),(4,5) of each field live in one 64-bit register pair and
// are updated with add/sub/fma.rn.f32x2; SMEM x-neighbor mirrors are 64-bit
// (one LDS.64/STS.64 per pair). Scalar math remains only for ghost rows.
//
// Exchange (unchanged from R8): payload+iteration tag in one 16-byte
// st/ld.global.cg.v4 chunk, slot = iteration parity; tag==i-1 equality poll;
// producer overwrite of slot i&1 cannot race a lagging reader because entry
// into iter i data-depends on the neighbor having consumed slot (i-2).
//
// Output layout (reference): (NT, NREC, 2*B):
//   out[t*NREC*8 + r*8 + comp*4 + b], comp 0 = vx, comp 1 = vz.
// ---------------------------------------------------------------------------

namespace {
constexpr int B_    = 4;
constexpr int NT_   = 256;
constexpr int NZ_   = 192;
constexpr int NX_   = 192;
constexpr int NREC_ = 128;
constexpr int RZ_   = 6;                 // rows per tile
constexpr int NP_   = 3;                 // row pairs per tile
constexpr int NTILES_ = NZ_ / RZ_;       // 32
constexpr int NCTA_   = B_ * NTILES_;    // 128 (< 148 SMs -> all co-resident)
constexpr int NIT_    = NT_ / 2;         // 128 iterations
constexpr float DT_ = 0.001f;
constexpr float DH_ = 10.0f;
}

using ull = unsigned long long;

struct __align__(16) Chunk { float a, b, c; int tag; };

// double-buffered tagged message chunks: [slot][cta][chunk 0..2][x]
__device__ Chunk g_dnC[2][NCTA_][3][NX_];
__device__ Chunk g_upC[2][NCTA_][3][NX_];

// ---- packed f32x2 helpers ----
__device__ __forceinline__ ull pk2(float lo, float hi) {
    ull r; asm("mov.b64 %0, {%1,%2};" : "=l"(r) : "f"(lo), "f"(hi)); return r;
}
__device__ __forceinline__ void up2(ull v, float& lo, float& hi) {
    asm("mov.b64 {%0,%1}, %2;" : "=f"(lo), "=f"(hi) : "l"(v));
}
__device__ __forceinline__ ull add2(ull a, ull b) {
    ull d; asm("add.rn.f32x2 %0,%1,%2;" : "=l"(d) : "l"(a), "l"(b)); return d;
}
__device__ __forceinline__ ull sub2(ull a, ull b) {
    ull d; asm("sub.rn.f32x2 %0,%1,%2;" : "=l"(d) : "l"(a), "l"(b)); return d;
}
__device__ __forceinline__ ull fma2(ull a, ull b, ull c) {
    ull d; asm("fma.rn.f32x2 %0,%1,%2,%3;" : "=l"(d) : "l"(a), "l"(b), "l"(c)); return d;
}

__device__ __forceinline__ void ldcg_v4(const Chunk* p, float& a, float& b,
                                        float& c, int& t) {
    asm volatile("ld.global.cg.v4.b32 {%0,%1,%2,%3}, [%4];"
                 : "=f"(a), "=f"(b), "=f"(c), "=r"(t) : "l"(p));
}
__device__ __forceinline__ void stcg_v4(Chunk* p, float a, float b, float c, int t) {
    asm volatile("st.global.cg.v4.b32 [%0], {%1,%2,%3,%4};"
                 :: "l"(p), "f"(a), "f"(b), "f"(c), "r"(t) : "memory");
}

__global__ void init_msgs_kernel() {
    int i = blockIdx.x * blockDim.x + threadIdx.x;
    int n = 2 * NCTA_ * 3 * NX_ * 4;            // total 32-bit words per array
    if (i < n) {
        ((int*)g_dnC)[i] = 0;
        ((int*)g_upC)[i] = 0;
    }
}

__global__ void __launch_bounds__(NX_, 1) wave_kernel(
    const float* __restrict__ xsrc,    // (B, NT)
    const float* __restrict__ vp,      // (NZ, NX)
    const float* __restrict__ vs,
    const float* __restrict__ rho,
    const int*   __restrict__ src_loc, // (B, 2)
    const int*   __restrict__ rec_loc, // (NREC, 2)
    float*       __restrict__ out)     // (NT, NREC, 2*B)
{
    const int c  = blockIdx.x;
    const int b  = c / NTILES_;
    const int tz = c % NTILES_;
    const int x  = threadIdx.x;
    const bool has_top = (tz > 0);
    const bool has_bot = (tz < NTILES_ - 1);
    const int xm = (x == 0) ? 0 : x - 1;              // clamp -> zero diff at edge
    const int xp = (x == NX_ - 1) ? NX_ - 1 : x + 1;

    // packed x-neighbor mirrors: [pair][x] = {row 2p (lo), row 2p+1 (hi)}
    __shared__ ull s_vx2 [NP_][NX_];
    __shared__ ull s_vz2 [NP_][NX_];
    __shared__ ull s_txx2[NP_][NX_];
    __shared__ ull s_txz2[NP_][NX_];
    // ghost staging rows (x-shifted reads of computed ghosts)
    __shared__ float sh_vxa1[NX_], sh_vza1[NX_], sh_txza1[NX_];
    __shared__ float sh_vxp1[NX_], sh_vzp1[NX_], sh_txxp1[NX_];

    // per-cell material coefficients (DT, 1/DH folded in), packed per pair
    ull bc2[NP_], cl2m2[NP_], clam2[NP_], cmu2[NP_];
    {
        float bcs[RZ_], cl2ms[RZ_], clams[RZ_], cmus[RZ_];
        #pragma unroll
        for (int r = 0; r < RZ_; ++r) {
            int gi = (tz * RZ_ + r) * NX_ + x;
            float vpv = __ldg(&vp[gi]);
            float vsv = __ldg(&vs[gi]);
            float rh  = __ldg(&rho[gi]);
            float mu  = rh * vsv * vsv;
            float lam = rh * (vpv * vpv - 2.0f * vsv * vsv);
            bcs[r]   = DT_ / (rh * DH_);
            cl2ms[r] = (DT_ / DH_) * (lam + 2.0f * mu);
            clams[r] = (DT_ / DH_) * lam;
            cmus[r]  = (DT_ / DH_) * mu;
        }
        #pragma unroll
        for (int p = 0; p < NP_; ++p) {
            bc2[p]   = pk2(bcs[2*p],   bcs[2*p+1]);
            cl2m2[p] = pk2(cl2ms[2*p], cl2ms[2*p+1]);
            clam2[p] = pk2(clams[2*p], clams[2*p+1]);
            cmu2[p]  = pk2(cmus[2*p],  cmus[2*p+1]);
        }
    }
    // ghost-row coefficients: a=z0-1, b=z0-2 (top), p=z1+1, q=z1+2 (bottom)
    float bA=0, bB=0, clamA=0, cl2mA=0, cmuA=0;
    float bP=0, bQ=0, clamP=0, cl2mP=0, cmuP=0;
    if (has_top) {
        int ga = (tz * RZ_ - 1) * NX_ + x;
        int gb = (tz * RZ_ - 2) * NX_ + x;
        float vpv = __ldg(&vp[ga]), vsv = __ldg(&vs[ga]), rh = __ldg(&rho[ga]);
        float mu  = rh * vsv * vsv;
        float lam = rh * (vpv * vpv - 2.0f * vsv * vsv);
        bA = DT_ / (rh * DH_);
        cl2mA = (DT_ / DH_) * (lam + 2.0f * mu);
        clamA = (DT_ / DH_) * lam;
        cmuA  = (DT_ / DH_) * mu;
        bB = DT_ / (__ldg(&rho[gb]) * DH_);
    }
    if (has_bot) {
        int gp = (tz * RZ_ + RZ_) * NX_ + x;
        int gq = (tz * RZ_ + RZ_ + 1) * NX_ + x;
        float vpv = __ldg(&vp[gp]), vsv = __ldg(&vs[gp]), rh = __ldg(&rho[gp]);
        float mu  = rh * vsv * vsv;
        float lam = rh * (vpv * vpv - 2.0f * vsv * vsv);
        bP = DT_ / (rh * DH_);
        cl2mP = (DT_ / DH_) * (lam + 2.0f * mu);
        clamP = (DT_ / DH_) * lam;
        cmuP  = (DT_ / DH_) * mu;
        bQ = DT_ / (__ldg(&rho[gq]) * DH_);
    }

    // wavefields, packed (lo=row 2p, hi=row 2p+1), zero initial conditions
    ull vx2[NP_]  = {0,0,0}, vz2[NP_]  = {0,0,0};
    ull txx2[NP_] = {0,0,0}, tzz2[NP_] = {0,0,0}, txz2[NP_] = {0,0,0};
    #pragma unroll
    for (int p = 0; p < NP_; ++p) {
        s_vx2[p][x] = 0ull; s_vz2[p][x] = 0ull;
        s_txx2[p][x] = 0ull; s_txz2[p][x] = 0ull;
    }

    // source ownership
    const int ssz = src_loc[2 * b];
    const int ssx = src_loc[2 * b + 1];
    const bool is_src = ((ssz / RZ_) == tz) && (x == ssx);
    const int src_lr   = ssz % RZ_;
    const int src_pair = src_lr >> 1;
    const bool src_hi  = (src_lr & 1) != 0;
    const bool src_at_a = has_top && (ssz == tz * RZ_ - 1)  && (x == ssx);
    const bool src_at_p = has_bot && (ssz == tz * RZ_ + RZ_) && (x == ssx);

    // receiver ownership: thread index doubles as receiver index
    bool is_rec = false;
    int rec_fidx = 0;                // float index into packed SMEM arrays
    if (x < NREC_) {
        int rz = rec_loc[2 * x];
        int rx = rec_loc[2 * x + 1];
        if ((rz / RZ_) == tz) {
            is_rec = true;
            int lrz = rz % RZ_;
            rec_fidx = ((lrz >> 1) * NX_ + rx) * 2 + (lrz & 1);
        }
    }
    const float* f_vx = reinterpret_cast<const float*>(&s_vx2[0][0]);
    const float* f_vz = reinterpret_cast<const float*>(&s_vz2[0][0]);

    __syncthreads();

    for (int i = 1; i <= NIT_; ++i) {
        const int t1 = 2 * i - 1;
        const int t2 = 2 * i;
        const float w1 = __ldg(&xsrc[b * NT_ + (t1 - 1)]);
        const float w2 = __ldg(&xsrc[b * NT_ + (t2 - 1)]);

        // unpack time-t stress edge scalars (also used by ghost math)
        float tzzL0,tzzH0,tzzL1,tzzH1,tzzL2,tzzH2;
        float txzL0,txzH0,txzL1,txzH1,txzL2,txzH2;
        up2(tzz2[0],tzzL0,tzzH0); up2(tzz2[1],tzzL1,tzzH1); up2(tzz2[2],tzzL2,tzzH2);
        up2(txz2[0],txzL0,txzH0); up2(txz2[1],txzL1,txzH1); up2(txz2[2],txzL2,txzH2);

        // ---- V1 pair1 (rows 2,3; no message dependence) + store ----
        {
            ull txz_zm = pk2(txzH0, txzL1);
            ull tzz_zp = pk2(tzzH1, tzzL2);
            vx2[1] = fma2(bc2[1], add2(sub2(s_txx2[1][xp], txx2[1]),
                                       sub2(txz2[1], txz_zm)), vx2[1]);
            vz2[1] = fma2(bc2[1], add2(sub2(txz2[1], s_txz2[1][xm]),
                                       sub2(tzz_zp, tzz2[1])), vz2[1]);
            s_vx2[1][x] = vx2[1]; s_vz2[1][x] = vz2[1];
        }

        // ---- per-lane tagged message poll (ONE RTT, no barrier) ----
        const int want = i - 1;
        const int pr = want & 1;
        float t_vx=0, t_txx_x=0, t_txz_x=0, t_txx_xp=0, t_txz_xm=0;
        float t_vz=0, t_tzz=0, t_txz2=0, t_txz2_xm=0, t_vz2=0, t_tzz2=0;
        float b_vx=0, b_txx_x=0, b_txz_x=0, b_txx_xp=0, b_txz_xm=0;
        float b_vz=0, b_tzz=0, b_vx2=0, b_txx2=0, b_txz2=0, b_tzz2=0, b_txx2_xp=0;
        {
            const Chunk* dn = has_top ? &g_dnC[pr][c - 1][0][0] : nullptr;
            const Chunk* up = has_bot ? &g_upC[pr][c + 1][0][0] : nullptr;
            bool top_ok = !has_top, bot_ok = !has_bot;
            do {
                if (!top_ok) {
                    int g0,g1,g2,g3,g4,g5; float u;
                    ldcg_v4(dn + 0*NX_ + x,  t_vx,   t_txx_x, t_txz_x,  g0);
                    ldcg_v4(dn + 0*NX_ + xm, u,      u,       t_txz_xm, g1);
                    ldcg_v4(dn + 0*NX_ + xp, u,      t_txx_xp,u,        g2);
                    ldcg_v4(dn + 1*NX_ + x,  t_vz,   t_tzz,   t_txz2,   g3);
                    ldcg_v4(dn + 1*NX_ + xm, u,      u,       t_txz2_xm,g4);
                    ldcg_v4(dn + 2*NX_ + x,  t_vz2,  t_tzz2,  u,        g5);
                    top_ok = (g0==want)&(g1==want)&(g2==want)&(g3==want)&(g4==want)&(g5==want);
                }
                if (!bot_ok) {
                    int g0,g1,g2,g3,g4,g5; float u;
                    ldcg_v4(up + 0*NX_ + x,  b_vx,   b_txx_x, b_txz_x,  g0);
                    ldcg_v4(up + 0*NX_ + xm, u,      u,       b_txz_xm, g1);
                    ldcg_v4(up + 0*NX_ + xp, u,      b_txx_xp,u,        g2);
                    ldcg_v4(up + 1*NX_ + x,  b_vz,   b_tzz,   b_vx2,    g3);
                    ldcg_v4(up + 2*NX_ + x,  b_txx2, b_txz2,  b_tzz2,   g4);
                    ldcg_v4(up + 2*NX_ + xp, b_txx2_xp, u,    u,        g5);
                    bot_ok = (g0==want)&(g1==want)&(g2==want)&(g3==want)&(g4==want)&(g5==want);
                }
            } while (!(top_ok && bot_ok));
        }
        const float tzz0_t = tzzL0;     // tzz[0] at time t
        const float txz5_t = txzH2;     // txz[5] at time t

        // ---- ghost t+1 velocities (fmaf order mirrors packed V) ----
        float vza1=0, vzb1=0, vxa1=0, vxp1=0, vxq1=0, vzp1=0;
        if (has_top) {
            vza1 = fmaf(bA, (t_txz_x  - t_txz_xm)  + (tzz0_t - t_tzz),  t_vz);
            vzb1 = fmaf(bB, (t_txz2   - t_txz2_xm) + (t_tzz  - t_tzz2), t_vz2);
            vxa1 = fmaf(bA, (t_txx_xp - t_txx_x)   + (t_txz_x - t_txz2), t_vx);
        }
        if (has_bot) {
            vxp1 = fmaf(bP, (b_txx_xp  - b_txx_x)  + (b_txz_x - txz5_t), b_vx);
            vxq1 = fmaf(bQ, (b_txx2_xp - b_txx2)   + (b_txz2  - b_txz_x), b_vx2);
            vzp1 = fmaf(bP, (b_txz_x   - b_txz_xm) + (b_tzz2  - b_tzz),  b_vz);
        }

        // ---- V1 pairs 0, 2 (message-dependent ghosts) + stores ----
        {
            ull txz_zm0 = pk2(has_top ? t_txz_x : txzL0, txzL0);
            ull tzz_zp0 = pk2(tzzH0, tzzL1);
            vx2[0] = fma2(bc2[0], add2(sub2(s_txx2[0][xp], txx2[0]),
                                       sub2(txz2[0], txz_zm0)), vx2[0]);
            vz2[0] = fma2(bc2[0], add2(sub2(txz2[0], s_txz2[0][xm]),
                                       sub2(tzz_zp0, tzz2[0])), vz2[0]);
            ull txz_zm2 = pk2(txzH1, txzL2);
            ull tzz_zp2 = pk2(tzzH2, has_bot ? b_tzz : tzzH2);
            vx2[2] = fma2(bc2[2], add2(sub2(s_txx2[2][xp], txx2[2]),
                                       sub2(txz2[2], txz_zm2)), vx2[2]);
            vz2[2] = fma2(bc2[2], add2(sub2(txz2[2], s_txz2[2][xm]),
                                       sub2(tzz_zp2, tzz2[2])), vz2[2]);
            s_vx2[0][x] = vx2[0]; s_vz2[0][x] = vz2[0];
            s_vx2[2][x] = vx2[2]; s_vz2[2][x] = vz2[2];
        }
        // velocity edge scalars at t+1 (for ghost stresses)
        float vxL0_1, vxH0_1, vzL2_1, vzH2_1;
        up2(vx2[0], vxL0_1, vxH0_1);
        up2(vz2[2], vzL2_1, vzH2_1);
        sh_vxa1[x] = vxa1; sh_vza1[x] = vza1;
        sh_vxp1[x] = vxp1; sh_vzp1[x] = vzp1;
        __syncthreads();   // (2)

        // record t1
        if (is_rec) {
            int base = (t1 - 1) * (NREC_ * 2 * B_) + x * (2 * B_);
            out[base + b]      = f_vx[rec_fidx];
            out[base + B_ + b] = f_vz[rec_fidx];
        }

        // ---- ghost t+1 edge stresses (fmaf order mirrors packed S) ----
        float tzza1=0, txza1=0, txxp1=0, tzzp1=0, txzp1=0;
        if (has_top) {
            float dvxa = vxa1 - sh_vxa1[xm];
            float dvza = vza1 - vzb1;
            tzza1 = fmaf(clamA, dvxa, fmaf(cl2mA, dvza, t_tzz));
            if (src_at_a) tzza1 += w1;
            txza1 = fmaf(cmuA, (vxL0_1 - vxa1) + (sh_vza1[xp] - vza1), t_txz_x);
        }
        if (has_bot) {
            float dvxp = vxp1 - sh_vxp1[xm];
            float dvzp = vzp1 - vzH2_1;
            txxp1 = fmaf(cl2mP, dvxp, fmaf(clamP, dvzp, b_txx_x));
            tzzp1 = fmaf(clamP, dvxp, fmaf(cl2mP, dvzp, b_tzz));
            if (src_at_p) { txxp1 += w1; tzzp1 += w1; }
            txzp1 = fmaf(cmuP, (vxq1 - vxp1) + (sh_vzp1[xp] - vzp1), b_txz_x);
        }

        // ------------------ S1 (packed, 3 pairs) ------------------
        {
            float vxL0,vxH0,vxL1,vxH1,vxL2,vxH2, vzL0,vzH0,vzL1,vzH1,vzL2,vzH2;
            up2(vx2[0],vxL0,vxH0); up2(vx2[1],vxL1,vxH1); up2(vx2[2],vxL2,vxH2);
            up2(vz2[0],vzL0,vzH0); up2(vz2[1],vzL1,vzH1); up2(vz2[2],vzL2,vzH2);
            ull vz_zm0 = pk2(has_top ? vza1 : vzL0, vzL0);
            ull vz_zm1 = pk2(vzH0, vzL1);
            ull vz_zm2 = pk2(vzH1, vzL2);
            ull vx_zp0 = pk2(vxH0, vxL1);
            ull vx_zp1 = pk2(vxH1, vxL2);
            ull vx_zp2 = pk2(vxH2, has_bot ? vxp1 : vxH2);
            #pragma unroll
            for (int p = 0; p < NP_; ++p) {
                ull vz_zm = (p == 0) ? vz_zm0 : (p == 1) ? vz_zm1 : vz_zm2;
                ull vx_zp = (p == 0) ? vx_zp0 : (p == 1) ? vx_zp1 : vx_zp2;
                ull dvx2 = sub2(vx2[p], s_vx2[p][xm]);
                ull dvz2 = sub2(vz2[p], vz_zm);
                txx2[p] = fma2(cl2m2[p], dvx2, fma2(clam2[p], dvz2, txx2[p]));
                tzz2[p] = fma2(clam2[p], dvx2, fma2(cl2m2[p], dvz2, tzz2[p]));
                txz2[p] = fma2(cmu2[p], add2(sub2(vx_zp, vx2[p]),
                                             sub2(s_vz2[p][xp], vz2[p])), txz2[p]);
                if (is_src && src_pair == p) {
                    float lo, hi;
                    up2(txx2[p], lo, hi); if (src_hi) hi += w1; else lo += w1;
                    txx2[p] = pk2(lo, hi);
                    up2(tzz2[p], lo, hi); if (src_hi) hi += w1; else lo += w1;
                    tzz2[p] = pk2(lo, hi);
                }
                s_txx2[p][x] = txx2[p]; s_txz2[p][x] = txz2[p];
            }
        }
        sh_txza1[x] = txza1; sh_txxp1[x] = txxp1;
        __syncthreads();   // (3)

        // fresh stress edge scalars at t+1
        up2(tzz2[0],tzzL0,tzzH0); up2(tzz2[1],tzzL1,tzzH1); up2(tzz2[2],tzzL2,tzzH2);
        up2(txz2[0],txzL0,txzH0); up2(txz2[1],txzL1,txzH1); up2(txz2[2],txzL2,txzH2);

        // ---- ghost t+2 edge velocities ----
        float vza2 = 0, vxp2 = 0;
        if (has_top)
            vza2 = fmaf(bA, (txza1 - sh_txza1[xm]) + (tzzL0 - tzza1), vza1);
        if (has_bot)
            vxp2 = fmaf(bP, (sh_txxp1[xp] - txxp1) + (txzp1 - txzH2), vxp1);

        // ------------------ V2 (packed, 3 pairs) ------------------
        {
            ull txz_zm0 = pk2(has_top ? txza1 : txzL0, txzL0);
            ull tzz_zp0 = pk2(tzzH0, tzzL1);
            ull txz_zm1 = pk2(txzH0, txzL1);
            ull tzz_zp1 = pk2(tzzH1, tzzL2);
            ull txz_zm2 = pk2(txzH1, txzL2);
            ull tzz_zp2 = pk2(tzzH2, has_bot ? tzzp1 : tzzH2);
            #pragma unroll
            for (int p = 0; p < NP_; ++p) {
                ull txz_zm = (p == 0) ? txz_zm0 : (p == 1) ? txz_zm1 : txz_zm2;
                ull tzz_zp = (p == 0) ? tzz_zp0 : (p == 1) ? tzz_zp1 : tzz_zp2;
                vx2[p] = fma2(bc2[p], add2(sub2(s_txx2[p][xp], txx2[p]),
                                           sub2(txz2[p], txz_zm)), vx2[p]);
                vz2[p] = fma2(bc2[p], add2(sub2(txz2[p], s_txz2[p][xm]),
                                           sub2(tzz_zp, tzz2[p])), vz2[p]);
                s_vx2[p][x] = vx2[p]; s_vz2[p][x] = vz2[p];
            }
        }
        __syncthreads();   // (4)

        // ---- S2 apron pairs {0, 2} first, then publish ----
        {
            float vxL0,vxH0,vxL1,vxH1,vxL2,vxH2, vzL0,vzH0,vzL1,vzH1,vzL2,vzH2;
            up2(vx2[0],vxL0,vxH0); up2(vx2[1],vxL1,vxH1); up2(vx2[2],vxL2,vxH2);
            up2(vz2[0],vzL0,vzH0); up2(vz2[1],vzL1,vzH1); up2(vz2[2],vzL2,vzH2);
            // pair 0
            {
                ull vz_zm = pk2(has_top ? vza2 : vzL0, vzL0);
                ull vx_zp = pk2(vxH0, vxL1);
                ull dvx2 = sub2(vx2[0], s_vx2[0][xm]);
                ull dvz2 = sub2(vz2[0], vz_zm);
                txx2[0] = fma2(cl2m2[0], dvx2, fma2(clam2[0], dvz2, txx2[0]));
                tzz2[0] = fma2(clam2[0], dvx2, fma2(cl2m2[0], dvz2, tzz2[0]));
                txz2[0] = fma2(cmu2[0], add2(sub2(vx_zp, vx2[0]),
                                             sub2(s_vz2[0][xp], vz2[0])), txz2[0]);
                if (is_src && src_pair == 0) {
                    float lo, hi;
                    up2(txx2[0], lo, hi); if (src_hi) hi += w2; else lo += w2;
                    txx2[0] = pk2(lo, hi);
                    up2(tzz2[0], lo, hi); if (src_hi) hi += w2; else lo += w2;
                    tzz2[0] = pk2(lo, hi);
                }
            }
            // pair 2
            {
                ull vz_zm = pk2(vzH1, vzL2);
                ull vx_zp = pk2(vxH2, has_bot ? vxp2 : vxH2);
                ull dvx2 = sub2(vx2[2], s_vx2[2][xm]);
                ull dvz2 = sub2(vz2[2], vz_zm);
                txx2[2] = fma2(cl2m2[2], dvx2, fma2(clam2[2], dvz2, txx2[2]));
                tzz2[2] = fma2(clam2[2], dvx2, fma2(cl2m2[2], dvz2, tzz2[2]));
                txz2[2] = fma2(cmu2[2], add2(sub2(vx_zp, vx2[2]),
                                             sub2(s_vz2[2][xp], vz2[2])), txz2[2]);
                if (is_src && src_pair == 2) {
                    float lo, hi;
                    up2(txx2[2], lo, hi); if (src_hi) hi += w2; else lo += w2;
                    txx2[2] = pk2(lo, hi);
                    up2(tzz2[2], lo, hi); if (src_hi) hi += w2; else lo += w2;
                    tzz2[2] = pk2(lo, hi);
                }
            }
            // publish t+2 apron, tag = i (per-lane, no barrier, no flag)
            {
                float txxL0,txxH0,txxL2,txxH2, tzzL0p,tzzH0p,tzzL2p,tzzH2p;
                float txzL0p,txzH0p,txzL2p,txzH2p;
                up2(txx2[0],txxL0,txxH0);   up2(txx2[2],txxL2,txxH2);
                up2(tzz2[0],tzzL0p,tzzH0p); up2(tzz2[2],tzzL2p,tzzH2p);
                up2(txz2[0],txzL0p,txzH0p); up2(txz2[2],txzL2p,txzH2p);
                const int pw = i & 1;
                Chunk* dn = &g_dnC[pw][c][0][0];
                stcg_v4(dn + 0*NX_ + x, vxH2,  txxH2,  txzH2p, i);
                stcg_v4(dn + 1*NX_ + x, vzH2,  tzzH2p, txzL2p, i);
                stcg_v4(dn + 2*NX_ + x, vzL2,  tzzL2p, 0.f,    i);
                Chunk* up = &g_upC[pw][c][0][0];
                stcg_v4(up + 0*NX_ + x, vxL0,  txxL0,  txzL0p, i);
                stcg_v4(up + 1*NX_ + x, vzL0,  tzzL0p, vxH0,   i);
                stcg_v4(up + 2*NX_ + x, txxH0, txzH0p, tzzH0p, i);
            }
            // record t2 (s_vx2/s_vz2 valid since sync 4; S2 doesn't touch them)
            if (is_rec) {
                int base = (t2 - 1) * (NREC_ * 2 * B_) + x * (2 * B_);
                out[base + b]      = f_vx[rec_fidx];
                out[base + B_ + b] = f_vz[rec_fidx];
            }
            // ---- S2 interior pair 1 (off the inter-CTA critical path) ----
            {
                ull vz_zm = pk2(vzH0, vzL1);
                ull vx_zp = pk2(vxH1, vxL2);
                ull dvx2 = sub2(vx2[1], s_vx2[1][xm]);
                ull dvz2 = sub2(vz2[1], vz_zm);
                txx2[1] = fma2(cl2m2[1], dvx2, fma2(clam2[1], dvz2, txx2[1]));
                tzz2[1] = fma2(clam2[1], dvx2, fma2(cl2m2[1], dvz2, tzz2[1]));
                txz2[1] = fma2(cmu2[1], add2(sub2(vx_zp, vx2[1]),
                                             sub2(s_vz2[1][xp], vz2[1])), txz2[1]);
                if (is_src && src_pair == 1) {
                    float lo, hi;
                    up2(txx2[1], lo, hi); if (src_hi) hi += w2; else lo += w2;
                    txx2[1] = pk2(lo, hi);
                    up2(tzz2[1], lo, hi); if (src_hi) hi += w2; else lo += w2;
                    tzz2[1] = pk2(lo, hi);
                }
            }
        }
        #pragma unroll
        for (int p = 0; p < NP_; ++p) { s_txx2[p][x] = txx2[p]; s_txz2[p][x] = txz2[p]; }
        __syncthreads();   // (6) — next iter's V1 reads s_txx2/s_txz2
    }
}

extern "C" void kernel_launch(void* const* d_in, const int* in_sizes, int n_in,
                              void* d_out, int out_size) {
    const float* x   = (const float*)d_in[0];
    const float* vp  = (const float*)d_in[1];
    const float* vs  = (const float*)d_in[2];
    const float* rho = (const float*)d_in[3];
    const int* src   = (const int*)d_in[4];
    const int* rec   = (const int*)d_in[5];
    float* out = (float*)d_out;

    // re-zero message slots (tags -> 0) so every graph replay is identical
    int n = 2 * NCTA_ * 3 * NX_ * 4;
    init_msgs_kernel<<<(n + 255) / 256, 256>>>();
    wave_kernel<<<NCTA_, NX_>>>(x, vp, vs, rho, src, rec, out);
}